// round 1
// baseline (speedup 1.0000x reference)
#include <cuda_runtime.h>
#include <cuda_bf16.h>
#include <math.h>

#define NN 100000
#define NE 1600000

// -------- device scratch (allocation-free rule: __device__ globals) --------
__device__ float g_deg[NN];           // degree, then deg_inv (in place)
__device__ float g_bufA[NN * 64];     // yl = h @ Wl
__device__ float g_bufB[NN * 64];     // yr = h @ Wr + b
__device__ float g_agg[NN * 64];      // scatter-sum target
__device__ float g_h[NN * 64];        // layer activations

// ---------------------------------------------------------------------------
__global__ void zero_deg_kernel() {
    int i = blockIdx.x * blockDim.x + threadIdx.x;
    if (i < NN / 4) ((float4*)g_deg)[i] = make_float4(0.f, 0.f, 0.f, 0.f);
}

__global__ void zero_agg_kernel(int n4) {
    int i = blockIdx.x * blockDim.x + threadIdx.x;
    if (i < n4) ((float4*)g_agg)[i] = make_float4(0.f, 0.f, 0.f, 0.f);
}

__global__ void deg_count_kernel(const int* __restrict__ dst) {
    int e = blockIdx.x * blockDim.x + threadIdx.x;
    if (e < NE) atomicAdd(&g_deg[dst[e]], 1.0f);
}

__global__ void deg_invert_kernel() {
    int i = blockIdx.x * blockDim.x + threadIdx.x;
    if (i < NN) g_deg[i] = 1.0f / fmaxf(g_deg[i], 1.0f);
}

// ---------------------------------------------------------------------------
// Dual projection: yl = h @ Wl ; yr = h @ Wr + b.  DIN fixed at 64.
// Block = 64 threads, each owns one node row; h-tile staged in shared
// (padded to 65 to kill bank conflicts), W staged in shared twice (two
// passes) to stay under the 48KB static-smem limit.
template<int DOUT, bool FROM_GH>
__global__ void __launch_bounds__(64)
gemm_dual_kernel(const float* __restrict__ hx,
                 const float* __restrict__ Wl,
                 const float* __restrict__ Wr,
                 const float* __restrict__ bias) {
    __shared__ float sh[64][65];
    __shared__ float sW[64 * DOUT];

    const float* __restrict__ h = FROM_GH ? (const float*)g_h : hx;

    int t = threadIdx.x;           // 0..63
    int node0 = blockIdx.x * 64;

    // stage h tile (coalesced: thread t loads column t of each row)
    for (int i = 0; i < 64; i++) {
        int n = node0 + i;
        sh[i][t] = (n < NN) ? h[(size_t)n * 64 + t] : 0.f;
    }
    // stage Wl
    for (int i = t; i < 64 * DOUT; i += 64) sW[i] = Wl[i];
    __syncthreads();

    int n = node0 + t;
    float acc[DOUT];

    if (n < NN) {
#pragma unroll
        for (int j = 0; j < DOUT; j++) acc[j] = 0.f;
        for (int k = 0; k < 64; k++) {
            float hk = sh[t][k];
#pragma unroll
            for (int j = 0; j < DOUT; j++) acc[j] += hk * sW[k * DOUT + j];
        }
#pragma unroll
        for (int j = 0; j < DOUT; j++) g_bufA[(size_t)n * DOUT + j] = acc[j];
    }
    __syncthreads();

    // stage Wr, second pass
    for (int i = t; i < 64 * DOUT; i += 64) sW[i] = Wr[i];
    __syncthreads();

    if (n < NN) {
#pragma unroll
        for (int j = 0; j < DOUT; j++) acc[j] = bias[j];
        for (int k = 0; k < 64; k++) {
            float hk = sh[t][k];
#pragma unroll
            for (int j = 0; j < DOUT; j++) acc[j] += hk * sW[k * DOUT + j];
        }
#pragma unroll
        for (int j = 0; j < DOUT; j++) g_bufB[(size_t)n * DOUT + j] = acc[j];
    }
}

// ---------------------------------------------------------------------------
// Scatter-sum of projected features: agg[dst] += yl[src].
// F4 = feature-dim / 4.  One thread per (edge, float4-chunk); vector RED
// atomics (sm_90+ atomicAdd(float4*)) quarter the atomic op count.
template<int F4>
__global__ void aggregate_kernel(const int* __restrict__ src,
                                 const int* __restrict__ dst) {
    int tid = blockIdx.x * blockDim.x + threadIdx.x;
    if (tid >= NE * F4) return;
    int e = tid >> (F4 == 16 ? 4 : 3);
    int j = tid & (F4 - 1);
    int s = src[e];
    int d = dst[e];
    float4 v = ((const float4*)g_bufA)[(size_t)s * F4 + j];
    atomicAdd(((float4*)g_agg) + (size_t)d * F4 + j, v);
}

// ---------------------------------------------------------------------------
// out = [ELU](agg * deg_inv + yr)
template<int F, bool DO_ELU, bool TO_GH>
__global__ void finalize_kernel(float* __restrict__ out_param) {
    constexpr int F4 = F / 4;
    int idx = blockIdx.x * blockDim.x + threadIdx.x;
    if (idx >= NN * F4) return;
    int node = idx / F4;
    float di = g_deg[node];
    float4 a = ((const float4*)g_agg)[idx];
    float4 r = ((const float4*)g_bufB)[idx];
    float4 o;
    o.x = fmaf(a.x, di, r.x);
    o.y = fmaf(a.y, di, r.y);
    o.z = fmaf(a.z, di, r.z);
    o.w = fmaf(a.w, di, r.w);
    if (DO_ELU) {
        o.x = (o.x > 0.f) ? o.x : expm1f(o.x);
        o.y = (o.y > 0.f) ? o.y : expm1f(o.y);
        o.z = (o.z > 0.f) ? o.z : expm1f(o.z);
        o.w = (o.w > 0.f) ? o.w : expm1f(o.w);
    }
    float* out = TO_GH ? (float*)g_h : out_param;
    ((float4*)out)[idx] = o;
}

// ---------------------------------------------------------------------------
extern "C" void kernel_launch(void* const* d_in, const int* in_sizes, int n_in,
                              void* d_out, int out_size) {
    const float* x   = (const float*)d_in[0];
    const int*   ei  = (const int*)d_in[1];
    const float* Wl0 = (const float*)d_in[2];
    const float* Wr0 = (const float*)d_in[3];
    const float* b0  = (const float*)d_in[4];
    const float* Wl1 = (const float*)d_in[5];
    const float* Wr1 = (const float*)d_in[6];
    const float* b1  = (const float*)d_in[7];
    const float* Wl2 = (const float*)d_in[8];
    const float* Wr2 = (const float*)d_in[9];
    const float* b2  = (const float*)d_in[10];
    float* out = (float*)d_out;

    const int* src = ei;
    const int* dst = ei + NE;

    const int TPB = 256;
    const int gemm_blocks = (NN + 63) / 64;

    // degree (edge-structure only; once)
    zero_deg_kernel<<<(NN / 4 + TPB - 1) / TPB, TPB>>>();
    deg_count_kernel<<<(NE + TPB - 1) / TPB, TPB>>>(dst);
    deg_invert_kernel<<<(NN + TPB - 1) / TPB, TPB>>>();

    // ---- layer 0: 64 -> 64, ELU ----
    gemm_dual_kernel<64, false><<<gemm_blocks, 64>>>(x, Wl0, Wr0, b0);
    zero_agg_kernel<<<(NN * 16 + TPB - 1) / TPB, TPB>>>(NN * 16);
    aggregate_kernel<16><<<(NE * 16 + TPB - 1) / TPB, TPB>>>(src, dst);
    finalize_kernel<64, true, true><<<(NN * 16 + TPB - 1) / TPB, TPB>>>(nullptr);

    // ---- layer 1: 64 -> 64, ELU ----
    gemm_dual_kernel<64, true><<<gemm_blocks, 64>>>(nullptr, Wl1, Wr1, b1);
    zero_agg_kernel<<<(NN * 16 + TPB - 1) / TPB, TPB>>>(NN * 16);
    aggregate_kernel<16><<<(NE * 16 + TPB - 1) / TPB, TPB>>>(src, dst);
    finalize_kernel<64, true, true><<<(NN * 16 + TPB - 1) / TPB, TPB>>>(nullptr);

    // ---- layer 2: 64 -> 32, no activation, straight to d_out ----
    gemm_dual_kernel<32, true><<<gemm_blocks, 64>>>(nullptr, Wl2, Wr2, b2);
    zero_agg_kernel<<<(NN * 8 + TPB - 1) / TPB, TPB>>>(NN * 8);
    aggregate_kernel<8><<<(NE * 8 + TPB - 1) / TPB, TPB>>>(src, dst);
    finalize_kernel<32, false, false><<<(NN * 8 + TPB - 1) / TPB, TPB>>>(out);
}

// round 2
// speedup vs baseline: 1.2128x; 1.2128x over previous
#include <cuda_runtime.h>
#include <cuda_bf16.h>
#include <math.h>

#define NN 100000
#define NE 1600000

// -------- device scratch (allocation-free rule: __device__ globals) --------
__device__ float g_deg[NN];           // degree, then deg_inv (in place)
__device__ float g_bufA[NN * 64];     // yl = h @ Wl
__device__ float g_bufB[NN * 64];     // yr = h @ Wr + b
__device__ float g_agg[NN * 64];      // scatter-sum target
__device__ float g_h[NN * 64];        // layer activations

// ---------------------------------------------------------------------------
__global__ void zero_deg_kernel() {
    int i = blockIdx.x * blockDim.x + threadIdx.x;
    if (i < NN / 4) ((float4*)g_deg)[i] = make_float4(0.f, 0.f, 0.f, 0.f);
}

__global__ void zero_agg_kernel(int n4) {
    int i = blockIdx.x * blockDim.x + threadIdx.x;
    if (i < n4) ((float4*)g_agg)[i] = make_float4(0.f, 0.f, 0.f, 0.f);
}

__global__ void deg_count_kernel(const int* __restrict__ dst) {
    int e = blockIdx.x * blockDim.x + threadIdx.x;
    if (e < NE) atomicAdd(&g_deg[dst[e]], 1.0f);
}

__global__ void deg_invert_kernel() {
    int i = blockIdx.x * blockDim.x + threadIdx.x;
    if (i < NN) g_deg[i] = 1.0f / fmaxf(g_deg[i], 1.0f);
}

// ---------------------------------------------------------------------------
// Dual projection: yl = h @ Wl ; yr = h @ Wr + b.  DIN fixed at 64.
//
// Layout: 32 nodes per block, DOUT/8 warps; warp w owns j-slice [8w, 8w+8),
// lane owns node (node0+lane). Per thread: 8+8 accumulators (both GEMMs in
// one k-loop over the shared h tile). W reads are warp-uniform (LDS broadcast),
// h reads are stride-65 (conflict-free). NN % 32 == 0, so no bounds checks.
template<int DOUT, bool FROM_GH>
__global__ void __launch_bounds__(32 * (DOUT / 8))
gemm_dual_kernel(const float* __restrict__ hx,
                 const float* __restrict__ Wl,
                 const float* __restrict__ Wr,
                 const float* __restrict__ bias) {
    __shared__ float sh[32][65];
    __shared__ alignas(16) float sWl[64 * DOUT];
    __shared__ alignas(16) float sWr[64 * DOUT];

    const float* __restrict__ h = FROM_GH ? (const float*)g_h : hx;

    const int t    = threadIdx.x;
    const int lane = t & 31;
    const int jq   = t >> 5;            // warp id = j-slice
    const int node0 = blockIdx.x * 32;
    const int nthreads = 32 * (DOUT / 8);

    // stage h tile (coalesced scalar loads; pad 65 keeps column reads clean)
    for (int i = t; i < 32 * 64; i += nthreads) {
        int r = i >> 6, c = i & 63;
        sh[r][c] = h[(size_t)(node0 + r) * 64 + c];
    }
    // stage both weight matrices
    for (int i = t; i < 64 * DOUT; i += nthreads) {
        sWl[i] = Wl[i];
        sWr[i] = Wr[i];
    }
    __syncthreads();

    float al[8], ar[8];
#pragma unroll
    for (int j = 0; j < 8; j++) {
        al[j] = 0.f;
        ar[j] = bias[jq * 8 + j];
    }

#pragma unroll 8
    for (int k = 0; k < 64; k++) {
        float hk = sh[lane][k];
        const float4 wl0 = *(const float4*)&sWl[k * DOUT + jq * 8];
        const float4 wl1 = *(const float4*)&sWl[k * DOUT + jq * 8 + 4];
        const float4 wr0 = *(const float4*)&sWr[k * DOUT + jq * 8];
        const float4 wr1 = *(const float4*)&sWr[k * DOUT + jq * 8 + 4];
        al[0] = fmaf(hk, wl0.x, al[0]);
        al[1] = fmaf(hk, wl0.y, al[1]);
        al[2] = fmaf(hk, wl0.z, al[2]);
        al[3] = fmaf(hk, wl0.w, al[3]);
        al[4] = fmaf(hk, wl1.x, al[4]);
        al[5] = fmaf(hk, wl1.y, al[5]);
        al[6] = fmaf(hk, wl1.z, al[6]);
        al[7] = fmaf(hk, wl1.w, al[7]);
        ar[0] = fmaf(hk, wr0.x, ar[0]);
        ar[1] = fmaf(hk, wr0.y, ar[1]);
        ar[2] = fmaf(hk, wr0.z, ar[2]);
        ar[3] = fmaf(hk, wr0.w, ar[3]);
        ar[4] = fmaf(hk, wr1.x, ar[4]);
        ar[5] = fmaf(hk, wr1.y, ar[5]);
        ar[6] = fmaf(hk, wr1.z, ar[6]);
        ar[7] = fmaf(hk, wr1.w, ar[7]);
    }

    const size_t n = (size_t)(node0 + lane);
    float4* pa = (float4*)&g_bufA[n * DOUT + jq * 8];
    float4* pb = (float4*)&g_bufB[n * DOUT + jq * 8];
    pa[0] = make_float4(al[0], al[1], al[2], al[3]);
    pa[1] = make_float4(al[4], al[5], al[6], al[7]);
    pb[0] = make_float4(ar[0], ar[1], ar[2], ar[3]);
    pb[1] = make_float4(ar[4], ar[5], ar[6], ar[7]);
}

// ---------------------------------------------------------------------------
// Scatter-sum of projected features: agg[dst] += yl[src].
// F4 = feature-dim / 4.  One thread per (edge, float4-chunk); vector RED
// atomics (sm_90+ atomicAdd(float4*)) quarter the atomic op count.
template<int F4>
__global__ void aggregate_kernel(const int* __restrict__ src,
                                 const int* __restrict__ dst) {
    int tid = blockIdx.x * blockDim.x + threadIdx.x;
    if (tid >= NE * F4) return;
    int e = tid >> (F4 == 16 ? 4 : 3);
    int j = tid & (F4 - 1);
    int s = src[e];
    int d = dst[e];
    float4 v = ((const float4*)g_bufA)[(size_t)s * F4 + j];
    atomicAdd(((float4*)g_agg) + (size_t)d * F4 + j, v);
}

// ---------------------------------------------------------------------------
// out = [ELU](agg * deg_inv + yr)
template<int F, bool DO_ELU, bool TO_GH>
__global__ void finalize_kernel(float* __restrict__ out_param) {
    constexpr int F4 = F / 4;
    int idx = blockIdx.x * blockDim.x + threadIdx.x;
    if (idx >= NN * F4) return;
    int node = idx / F4;
    float di = g_deg[node];
    float4 a = ((const float4*)g_agg)[idx];
    float4 r = ((const float4*)g_bufB)[idx];
    float4 o;
    o.x = fmaf(a.x, di, r.x);
    o.y = fmaf(a.y, di, r.y);
    o.z = fmaf(a.z, di, r.z);
    o.w = fmaf(a.w, di, r.w);
    if (DO_ELU) {
        o.x = (o.x > 0.f) ? o.x : expm1f(o.x);
        o.y = (o.y > 0.f) ? o.y : expm1f(o.y);
        o.z = (o.z > 0.f) ? o.z : expm1f(o.z);
        o.w = (o.w > 0.f) ? o.w : expm1f(o.w);
    }
    float* out = TO_GH ? (float*)g_h : out_param;
    ((float4*)out)[idx] = o;
}

// ---------------------------------------------------------------------------
extern "C" void kernel_launch(void* const* d_in, const int* in_sizes, int n_in,
                              void* d_out, int out_size) {
    const float* x   = (const float*)d_in[0];
    const int*   ei  = (const int*)d_in[1];
    const float* Wl0 = (const float*)d_in[2];
    const float* Wr0 = (const float*)d_in[3];
    const float* b0  = (const float*)d_in[4];
    const float* Wl1 = (const float*)d_in[5];
    const float* Wr1 = (const float*)d_in[6];
    const float* b1  = (const float*)d_in[7];
    const float* Wl2 = (const float*)d_in[8];
    const float* Wr2 = (const float*)d_in[9];
    const float* b2  = (const float*)d_in[10];
    float* out = (float*)d_out;

    const int* src = ei;
    const int* dst = ei + NE;

    const int TPB = 256;
    const int gemm_blocks = NN / 32;   // 3125, exact

    // degree (edge-structure only; once)
    zero_deg_kernel<<<(NN / 4 + TPB - 1) / TPB, TPB>>>();
    deg_count_kernel<<<(NE + TPB - 1) / TPB, TPB>>>(dst);
    deg_invert_kernel<<<(NN + TPB - 1) / TPB, TPB>>>();

    // ---- layer 0: 64 -> 64, ELU ----
    gemm_dual_kernel<64, false><<<gemm_blocks, 256>>>(x, Wl0, Wr0, b0);
    zero_agg_kernel<<<(NN * 16 + TPB - 1) / TPB, TPB>>>(NN * 16);
    aggregate_kernel<16><<<(NE * 16 + TPB - 1) / TPB, TPB>>>(src, dst);
    finalize_kernel<64, true, true><<<(NN * 16 + TPB - 1) / TPB, TPB>>>(nullptr);

    // ---- layer 1: 64 -> 64, ELU ----
    gemm_dual_kernel<64, true><<<gemm_blocks, 256>>>(nullptr, Wl1, Wr1, b1);
    zero_agg_kernel<<<(NN * 16 + TPB - 1) / TPB, TPB>>>(NN * 16);
    aggregate_kernel<16><<<(NE * 16 + TPB - 1) / TPB, TPB>>>(src, dst);
    finalize_kernel<64, true, true><<<(NN * 16 + TPB - 1) / TPB, TPB>>>(nullptr);

    // ---- layer 2: 64 -> 32, no activation, straight to d_out ----
    gemm_dual_kernel<32, true><<<gemm_blocks, 128>>>(nullptr, Wl2, Wr2, b2);
    zero_agg_kernel<<<(NN * 8 + TPB - 1) / TPB, TPB>>>(NN * 8);
    aggregate_kernel<8><<<(NE * 8 + TPB - 1) / TPB, TPB>>>(src, dst);
    finalize_kernel<32, false, false><<<(NN * 8 + TPB - 1) / TPB, TPB>>>(out);
}

// round 3
// speedup vs baseline: 1.4673x; 1.2098x over previous
#include <cuda_runtime.h>
#include <cuda_bf16.h>
#include <math.h>

#define NN 100000
#define NE 1600000

// -------- device scratch (allocation-free rule: __device__ globals) --------
__device__ float g_deg[NN];                 // degree, then deg_inv (in place)
__device__ float g_bufA[NN * 64];           // yl = h @ Wl
__device__ float g_bufB[NN * 64];           // yr = h @ Wr + b
__device__ float g_agg[NN * 64];            // scatter-sum target
__device__ float g_h[NN * 64];              // layer activations

// ---------------------------------------------------------------------------
__global__ void zero_deg_kernel() {
    int i = blockIdx.x * blockDim.x + threadIdx.x;
    if (i < NN / 4) ((float4*)g_deg)[i] = make_float4(0.f, 0.f, 0.f, 0.f);
}

__global__ void zero_agg_kernel(int n4) {
    int i = blockIdx.x * blockDim.x + threadIdx.x;
    if (i < n4) ((float4*)g_agg)[i] = make_float4(0.f, 0.f, 0.f, 0.f);
}

__global__ void deg_count_kernel(const int* __restrict__ dst) {
    int e = blockIdx.x * blockDim.x + threadIdx.x;
    if (e < NE) atomicAdd(&g_deg[dst[e]], 1.0f);
}

__global__ void deg_invert_kernel() {
    int i = blockIdx.x * blockDim.x + threadIdx.x;
    if (i < NN) g_deg[i] = 1.0f / fmaxf(g_deg[i], 1.0f);
}

// ---------------------------------------------------------------------------
// Dual projection: yl = h @ Wl ; yr = h @ Wr + b.  DIN fixed at 64.
//
// Register tile: each thread owns 4 nodes x 4 j-outputs for BOTH matrices
// (32 FMA per k-step) fed by 3 x LDS.128 per k-step:
//   - h tile stored k-major in shared: sh[k][node]  -> one float4 = 4 nodes
//   - w slices contiguous: one float4 each from sWl / sWr
// Block = 256 threads; tile = NPB nodes x DOUT outputs.
//   DOUT=64: JG=16 j-groups, NPB=64 nodes,  smem = 16K(h) + 2*16K(w) = 48K
//   DOUT=32: JG=8  j-groups, NPB=128 nodes, smem = 32K(h) + 2*8K(w)  = 48K
template<int DOUT, bool FROM_GH>
__global__ void __launch_bounds__(256, 4)
gemm_dual_kernel(const float* __restrict__ hx,
                 const float* __restrict__ Wl,
                 const float* __restrict__ Wr,
                 const float* __restrict__ bias) {
    constexpr int JG  = DOUT / 4;        // j-groups of width 4
    constexpr int NPB = 256 / JG * 4;    // nodes per block (64 or 128)
    constexpr int KC  = 64 * NPB / 256;  // k's staged per thread (16 or 32)

    __shared__ alignas(16) float sh[64][NPB];     // k-major h tile
    __shared__ alignas(16) float sWl[64 * DOUT];
    __shared__ alignas(16) float sWr[64 * DOUT];

    const float* __restrict__ h = FROM_GH ? (const float*)g_h : hx;

    const int t     = threadIdx.x;
    const int node0 = blockIdx.x * NPB;

    // ---- stage h tile, transposing to k-major ----
    // thread t: node r = t % NPB, k-chunk c0 = (t / NPB) * KC
    {
        const int r  = t % NPB;
        const int c0 = (t / NPB) * KC;
        const int n  = node0 + r;
        const bool ok = (n < NN);
#pragma unroll
        for (int i = 0; i < KC; i += 4) {
            float4 v = ok ? *(const float4*)&h[(size_t)n * 64 + c0 + i]
                          : make_float4(0.f, 0.f, 0.f, 0.f);
            sh[c0 + i + 0][r] = v.x;   // lanes have consecutive r -> no conflicts
            sh[c0 + i + 1][r] = v.y;
            sh[c0 + i + 2][r] = v.z;
            sh[c0 + i + 3][r] = v.w;
        }
    }
    // ---- stage both weight matrices (coalesced) ----
    for (int i = t; i < 64 * DOUT; i += 256) {
        sWl[i] = Wl[i];
        sWr[i] = Wr[i];
    }
    __syncthreads();

    const int jg = t % JG;          // j-group (4 outputs)
    const int ng = t / JG;          // node-group (4 nodes)

    float aL[4][4], aR[4][4];
#pragma unroll
    for (int n = 0; n < 4; n++)
#pragma unroll
        for (int j = 0; j < 4; j++) {
            aL[n][j] = 0.f;
            aR[n][j] = bias[jg * 4 + j];
        }

#pragma unroll 8
    for (int k = 0; k < 64; k++) {
        const float4 hv = *(const float4*)&sh[k][ng * 4];
        const float4 wl = *(const float4*)&sWl[k * DOUT + jg * 4];
        const float4 wr = *(const float4*)&sWr[k * DOUT + jg * 4];
        const float hn[4] = {hv.x, hv.y, hv.z, hv.w};
        const float wlj[4] = {wl.x, wl.y, wl.z, wl.w};
        const float wrj[4] = {wr.x, wr.y, wr.z, wr.w};
#pragma unroll
        for (int n = 0; n < 4; n++) {
#pragma unroll
            for (int j = 0; j < 4; j++) {
                aL[n][j] = fmaf(hn[n], wlj[j], aL[n][j]);
                aR[n][j] = fmaf(hn[n], wrj[j], aR[n][j]);
            }
        }
    }

    // ---- epilogue: float4 stores, coalesced across jg ----
#pragma unroll
    for (int n = 0; n < 4; n++) {
        const int node = node0 + ng * 4 + n;
        if (node < NN) {
            *(float4*)&g_bufA[(size_t)node * DOUT + jg * 4] =
                make_float4(aL[n][0], aL[n][1], aL[n][2], aL[n][3]);
            *(float4*)&g_bufB[(size_t)node * DOUT + jg * 4] =
                make_float4(aR[n][0], aR[n][1], aR[n][2], aR[n][3]);
        }
    }
}

// ---------------------------------------------------------------------------
// Scatter-sum of projected features: agg[dst] += yl[src].
// F4 = feature-dim / 4.  One thread per (edge, float4-chunk); vector RED
// atomics (sm_90+ atomicAdd(float4*)) quarter the atomic op count.
template<int F4>
__global__ void aggregate_kernel(const int* __restrict__ src,
                                 const int* __restrict__ dst) {
    int tid = blockIdx.x * blockDim.x + threadIdx.x;
    if (tid >= NE * F4) return;
    int e = tid >> (F4 == 16 ? 4 : 3);
    int j = tid & (F4 - 1);
    int s = src[e];
    int d = dst[e];
    float4 v = ((const float4*)g_bufA)[(size_t)s * F4 + j];
    atomicAdd(((float4*)g_agg) + (size_t)d * F4 + j, v);
}

// ---------------------------------------------------------------------------
// out = [ELU](agg * deg_inv + yr)
template<int F, bool DO_ELU, bool TO_GH>
__global__ void finalize_kernel(float* __restrict__ out_param) {
    constexpr int F4 = F / 4;
    int idx = blockIdx.x * blockDim.x + threadIdx.x;
    if (idx >= NN * F4) return;
    int node = idx / F4;
    float di = g_deg[node];
    float4 a = ((const float4*)g_agg)[idx];
    float4 r = ((const float4*)g_bufB)[idx];
    float4 o;
    o.x = fmaf(a.x, di, r.x);
    o.y = fmaf(a.y, di, r.y);
    o.z = fmaf(a.z, di, r.z);
    o.w = fmaf(a.w, di, r.w);
    if (DO_ELU) {
        o.x = (o.x > 0.f) ? o.x : expm1f(o.x);
        o.y = (o.y > 0.f) ? o.y : expm1f(o.y);
        o.z = (o.z > 0.f) ? o.z : expm1f(o.z);
        o.w = (o.w > 0.f) ? o.w : expm1f(o.w);
    }
    float* out = TO_GH ? (float*)g_h : out_param;
    ((float4*)out)[idx] = o;
}

// ---------------------------------------------------------------------------
extern "C" void kernel_launch(void* const* d_in, const int* in_sizes, int n_in,
                              void* d_out, int out_size) {
    const float* x   = (const float*)d_in[0];
    const int*   ei  = (const int*)d_in[1];
    const float* Wl0 = (const float*)d_in[2];
    const float* Wr0 = (const float*)d_in[3];
    const float* b0  = (const float*)d_in[4];
    const float* Wl1 = (const float*)d_in[5];
    const float* Wr1 = (const float*)d_in[6];
    const float* b1  = (const float*)d_in[7];
    const float* Wl2 = (const float*)d_in[8];
    const float* Wr2 = (const float*)d_in[9];
    const float* b2  = (const float*)d_in[10];
    float* out = (float*)d_out;

    const int* src = ei;
    const int* dst = ei + NE;

    const int TPB = 256;
    const int gemm_blocks64 = (NN + 63) / 64;     // 1563
    const int gemm_blocks32 = (NN + 127) / 128;   // 782

    // degree (edge-structure only; once)
    zero_deg_kernel<<<(NN / 4 + TPB - 1) / TPB, TPB>>>();
    deg_count_kernel<<<(NE + TPB - 1) / TPB, TPB>>>(dst);
    deg_invert_kernel<<<(NN + TPB - 1) / TPB, TPB>>>();

    // ---- layer 0: 64 -> 64, ELU ----
    gemm_dual_kernel<64, false><<<gemm_blocks64, 256>>>(x, Wl0, Wr0, b0);
    zero_agg_kernel<<<(NN * 16 + TPB - 1) / TPB, TPB>>>(NN * 16);
    aggregate_kernel<16><<<(NE * 16 + TPB - 1) / TPB, TPB>>>(src, dst);
    finalize_kernel<64, true, true><<<(NN * 16 + TPB - 1) / TPB, TPB>>>(nullptr);

    // ---- layer 1: 64 -> 64, ELU ----
    gemm_dual_kernel<64, true><<<gemm_blocks64, 256>>>(nullptr, Wl1, Wr1, b1);
    zero_agg_kernel<<<(NN * 16 + TPB - 1) / TPB, TPB>>>(NN * 16);
    aggregate_kernel<16><<<(NE * 16 + TPB - 1) / TPB, TPB>>>(src, dst);
    finalize_kernel<64, true, true><<<(NN * 16 + TPB - 1) / TPB, TPB>>>(nullptr);

    // ---- layer 2: 64 -> 32, no activation, straight to d_out ----
    gemm_dual_kernel<32, true><<<gemm_blocks32, 256>>>(nullptr, Wl2, Wr2, b2);
    zero_agg_kernel<<<(NN * 8 + TPB - 1) / TPB, TPB>>>(NN * 8);
    aggregate_kernel<8><<<(NE * 8 + TPB - 1) / TPB, TPB>>>(src, dst);
    finalize_kernel<32, false, false><<<(NN * 8 + TPB - 1) / TPB, TPB>>>(out);
}

// round 4
// speedup vs baseline: 2.2226x; 1.5148x over previous
#include <cuda_runtime.h>
#include <cuda_bf16.h>
#include <math.h>

#define NN 100000
#define NE 1600000
#define SCAN_BS 512
#define NBLK ((NN + SCAN_BS - 1) / SCAN_BS)   // 196

// -------- device scratch (allocation-free rule: __device__ globals) --------
__device__ float g_deginv[NN];
__device__ int   g_degi[NN];
__device__ int   g_cursor[NN];
__device__ int   g_rowptr[NN + 1];
__device__ int   g_rowtmp[NN];
__device__ int   g_blocksum[NBLK];
__device__ int   g_blockoff[NBLK];
__device__ int   g_col[NE];                  // CSR: src ids grouped by dst
__device__ float g_bufA[NN * 64];            // yl = h @ Wl
__device__ float g_bufB[NN * 64];            // yr = h @ Wr + b
__device__ float g_h[NN * 64];               // layer activations

// ---------------------------------------------------------------------------
// CSR build (edge structure fixed across layers -> once per call)
// ---------------------------------------------------------------------------
__global__ void zero_int_kernel() {
    int i = blockIdx.x * blockDim.x + threadIdx.x;
    if (i < NN) { g_degi[i] = 0; g_cursor[i] = 0; }
}

__global__ void deg_count_kernel(const int* __restrict__ dst) {
    int e = blockIdx.x * blockDim.x + threadIdx.x;
    if (e < NE) atomicAdd(&g_degi[dst[e]], 1);
}

// block-level inclusive scan (Hillis-Steele) -> exclusive partials + block sums
__global__ void scan_a_kernel() {
    __shared__ int s[SCAN_BS];
    int t = threadIdx.x;
    int i = blockIdx.x * SCAN_BS + t;
    int v = (i < NN) ? g_degi[i] : 0;
    s[t] = v;
    __syncthreads();
#pragma unroll
    for (int off = 1; off < SCAN_BS; off <<= 1) {
        int x = (t >= off) ? s[t - off] : 0;
        __syncthreads();
        s[t] += x;
        __syncthreads();
    }
    if (i < NN) g_rowtmp[i] = s[t] - v;           // exclusive
    if (t == SCAN_BS - 1) g_blocksum[blockIdx.x] = s[t];
}

// single-block scan of block sums -> exclusive block offsets
__global__ void scan_b_kernel() {
    __shared__ int s[256];
    int t = threadIdx.x;
    int v = (t < NBLK) ? g_blocksum[t] : 0;
    s[t] = v;
    __syncthreads();
#pragma unroll
    for (int off = 1; off < 256; off <<= 1) {
        int x = (t >= off) ? s[t - off] : 0;
        __syncthreads();
        s[t] += x;
        __syncthreads();
    }
    if (t < NBLK) g_blockoff[t] = s[t] - v;       // exclusive
}

__global__ void scan_c_kernel() {
    int i = blockIdx.x * blockDim.x + threadIdx.x;
    if (i < NN) {
        g_rowptr[i] = g_rowtmp[i] + g_blockoff[i / SCAN_BS];
        g_deginv[i] = 1.0f / fmaxf((float)g_degi[i], 1.0f);
    }
    if (i == 0) g_rowptr[NN] = NE;
}

__global__ void csr_fill_kernel(const int* __restrict__ src,
                                const int* __restrict__ dst) {
    int e = blockIdx.x * blockDim.x + threadIdx.x;
    if (e >= NE) return;
    int d = dst[e];
    int pos = g_rowptr[d] + atomicAdd(&g_cursor[d], 1);
    g_col[pos] = src[e];
}

// ---------------------------------------------------------------------------
// Dual projection: yl = h @ Wl ; yr = h @ Wr + b.  DIN fixed at 64.
// (unchanged from round 3 — 4x4 register tile, k-major shared h)
template<int DOUT, bool FROM_GH>
__global__ void __launch_bounds__(256, 4)
gemm_dual_kernel(const float* __restrict__ hx,
                 const float* __restrict__ Wl,
                 const float* __restrict__ Wr,
                 const float* __restrict__ bias) {
    constexpr int JG  = DOUT / 4;
    constexpr int NPB = 256 / JG * 4;
    constexpr int KC  = 64 * NPB / 256;

    __shared__ alignas(16) float sh[64][NPB];
    __shared__ alignas(16) float sWl[64 * DOUT];
    __shared__ alignas(16) float sWr[64 * DOUT];

    const float* __restrict__ h = FROM_GH ? (const float*)g_h : hx;

    const int t     = threadIdx.x;
    const int node0 = blockIdx.x * NPB;

    {
        const int r  = t % NPB;
        const int c0 = (t / NPB) * KC;
        const int n  = node0 + r;
        const bool ok = (n < NN);
#pragma unroll
        for (int i = 0; i < KC; i += 4) {
            float4 v = ok ? *(const float4*)&h[(size_t)n * 64 + c0 + i]
                          : make_float4(0.f, 0.f, 0.f, 0.f);
            sh[c0 + i + 0][r] = v.x;
            sh[c0 + i + 1][r] = v.y;
            sh[c0 + i + 2][r] = v.z;
            sh[c0 + i + 3][r] = v.w;
        }
    }
    for (int i = t; i < 64 * DOUT; i += 256) {
        sWl[i] = Wl[i];
        sWr[i] = Wr[i];
    }
    __syncthreads();

    const int jg = t % JG;
    const int ng = t / JG;

    float aL[4][4], aR[4][4];
#pragma unroll
    for (int n = 0; n < 4; n++)
#pragma unroll
        for (int j = 0; j < 4; j++) {
            aL[n][j] = 0.f;
            aR[n][j] = bias[jg * 4 + j];
        }

#pragma unroll 8
    for (int k = 0; k < 64; k++) {
        const float4 hv = *(const float4*)&sh[k][ng * 4];
        const float4 wl = *(const float4*)&sWl[k * DOUT + jg * 4];
        const float4 wr = *(const float4*)&sWr[k * DOUT + jg * 4];
        const float hn[4]  = {hv.x, hv.y, hv.z, hv.w};
        const float wlj[4] = {wl.x, wl.y, wl.z, wl.w};
        const float wrj[4] = {wr.x, wr.y, wr.z, wr.w};
#pragma unroll
        for (int n = 0; n < 4; n++) {
#pragma unroll
            for (int j = 0; j < 4; j++) {
                aL[n][j] = fmaf(hn[n], wlj[j], aL[n][j]);
                aR[n][j] = fmaf(hn[n], wrj[j], aR[n][j]);
            }
        }
    }

#pragma unroll
    for (int n = 0; n < 4; n++) {
        const int node = node0 + ng * 4 + n;
        if (node < NN) {
            *(float4*)&g_bufA[(size_t)node * DOUT + jg * 4] =
                make_float4(aL[n][0], aL[n][1], aL[n][2], aL[n][3]);
            *(float4*)&g_bufB[(size_t)node * DOUT + jg * 4] =
                make_float4(aR[n][0], aR[n][1], aR[n][2], aR[n][3]);
        }
    }
}

// ---------------------------------------------------------------------------
// Fused gather + epilogue: out[n] = [ELU]( mean_{e in row(n)} yl[col[e]] + yr[n] )
// L = F/4 lanes per node, one float4 per lane. No atomics, no zeroing pass.
template<int F, bool DO_ELU, bool TO_GH>
__global__ void __launch_bounds__(256)
gather_kernel(float* __restrict__ out_param) {
    constexpr int L = F / 4;               // 16 (F=64) or 8 (F=32)
    const int t    = threadIdx.x;
    const int grp  = t / L;
    const int lane = t % L;
    const int node = blockIdx.x * (256 / L) + grp;
    if (node >= NN) return;

    const int beg = g_rowptr[node];
    const int end = g_rowptr[node + 1];
    const float4* __restrict__ A = (const float4*)g_bufA;

    float4 a0 = make_float4(0.f, 0.f, 0.f, 0.f);
    float4 a1 = make_float4(0.f, 0.f, 0.f, 0.f);
    int e = beg;
    for (; e + 2 <= end; e += 2) {
        int s0 = g_col[e];
        int s1 = g_col[e + 1];
        float4 v0 = A[(size_t)s0 * L + lane];
        float4 v1 = A[(size_t)s1 * L + lane];
        a0.x += v0.x; a0.y += v0.y; a0.z += v0.z; a0.w += v0.w;
        a1.x += v1.x; a1.y += v1.y; a1.z += v1.z; a1.w += v1.w;
    }
    if (e < end) {
        int s0 = g_col[e];
        float4 v0 = A[(size_t)s0 * L + lane];
        a0.x += v0.x; a0.y += v0.y; a0.z += v0.z; a0.w += v0.w;
    }

    const float di = g_deginv[node];
    const float4 r = ((const float4*)g_bufB)[(size_t)node * L + lane];
    float4 o;
    o.x = fmaf(a0.x + a1.x, di, r.x);
    o.y = fmaf(a0.y + a1.y, di, r.y);
    o.z = fmaf(a0.z + a1.z, di, r.z);
    o.w = fmaf(a0.w + a1.w, di, r.w);
    if (DO_ELU) {
        o.x = (o.x > 0.f) ? o.x : expm1f(o.x);
        o.y = (o.y > 0.f) ? o.y : expm1f(o.y);
        o.z = (o.z > 0.f) ? o.z : expm1f(o.z);
        o.w = (o.w > 0.f) ? o.w : expm1f(o.w);
    }
    float* out = TO_GH ? (float*)g_h : out_param;
    ((float4*)out)[(size_t)node * L + lane] = o;
}

// ---------------------------------------------------------------------------
extern "C" void kernel_launch(void* const* d_in, const int* in_sizes, int n_in,
                              void* d_out, int out_size) {
    const float* x   = (const float*)d_in[0];
    const int*   ei  = (const int*)d_in[1];
    const float* Wl0 = (const float*)d_in[2];
    const float* Wr0 = (const float*)d_in[3];
    const float* b0  = (const float*)d_in[4];
    const float* Wl1 = (const float*)d_in[5];
    const float* Wr1 = (const float*)d_in[6];
    const float* b1  = (const float*)d_in[7];
    const float* Wl2 = (const float*)d_in[8];
    const float* Wr2 = (const float*)d_in[9];
    const float* b2  = (const float*)d_in[10];
    float* out = (float*)d_out;

    const int* src = ei;
    const int* dst = ei + NE;

    const int TPB = 256;
    const int gemm_blocks64 = (NN + 63) / 64;
    const int gemm_blocks32 = (NN + 127) / 128;
    const int gather_blocks64 = (NN + 15) / 16;   // 16 nodes/block (L=16)
    const int gather_blocks32 = (NN + 31) / 32;   // 32 nodes/block (L=8)

    // ---- CSR build (once; structure shared by all layers) ----
    zero_int_kernel<<<(NN + TPB - 1) / TPB, TPB>>>();
    deg_count_kernel<<<(NE + TPB - 1) / TPB, TPB>>>(dst);
    scan_a_kernel<<<NBLK, SCAN_BS>>>();
    scan_b_kernel<<<1, 256>>>();
    scan_c_kernel<<<(NN + TPB - 1) / TPB, TPB>>>();
    csr_fill_kernel<<<(NE + TPB - 1) / TPB, TPB>>>(src, dst);

    // ---- layer 0: 64 -> 64, ELU ----
    gemm_dual_kernel<64, false><<<gemm_blocks64, 256>>>(x, Wl0, Wr0, b0);
    gather_kernel<64, true, true><<<gather_blocks64, 256>>>(nullptr);

    // ---- layer 1: 64 -> 64, ELU ----
    gemm_dual_kernel<64, true><<<gemm_blocks64, 256>>>(nullptr, Wl1, Wr1, b1);
    gather_kernel<64, true, true><<<gather_blocks64, 256>>>(nullptr);

    // ---- layer 2: 64 -> 32, no activation, straight to d_out ----
    gemm_dual_kernel<32, true><<<gemm_blocks32, 256>>>(nullptr, Wl2, Wr2, b2);
    gather_kernel<32, false, false><<<gather_blocks32, 256>>>(out);
}